// round 1
// baseline (speedup 1.0000x reference)
#include <cuda_runtime.h>
#include <cuda_bf16.h>

#define BB 64
#define LL 200
#define DD 128
#define MM 50
#define NQ 10000

// ---- device scratch (static allocation per harness rules) ----
__device__ float g_w[BB * LL * MM];          // softmax weights  [B,L,50]
__device__ float g_e[BB * LL * DD];          // sigmoid gate     [B,L,128]
__device__ float g_a[BB * LL * DD];          // tanh add         [B,L,128]
__device__ float g_rp[2][BB * LL * DD];      // partial reads (m-halves)

// ============================================================================
// Kernel A: per-token precompute: w = softmax(k Mk^T), e = sigma(v eW^T + eb),
//           a = tanh(v aW^T + ab).  One block per token, 128 threads.
// ============================================================================
__global__ void precompute_kernel(
    const int* __restrict__ q, const int* __restrict__ r,
    const float* __restrict__ k_emb, const float* __restrict__ v_emb,
    const float* __restrict__ Mk,
    const float* __restrict__ e_W, const float* __restrict__ e_b,
    const float* __restrict__ a_W, const float* __restrict__ a_b)
{
    int bl = blockIdx.x;
    int tid = threadIdx.x;
    __shared__ alignas(16) float k_s[DD];
    __shared__ alignas(16) float v_s[DD];
    __shared__ float logits[MM];
    __shared__ float red[2];

    int qi = q[bl];
    int xi = qi + NQ * r[bl];
    k_s[tid] = k_emb[qi * DD + tid];
    v_s[tid] = v_emb[xi * DD + tid];
    __syncthreads();

    int warp = tid >> 5, lane = tid & 31;
    // logits[m] = k . Mk[m]  (warp-per-m, coalesced Mk reads)
    for (int m = warp; m < MM; m += 4) {
        float s = 0.f;
        #pragma unroll
        for (int ss = 0; ss < 4; ss++)
            s += k_s[lane + 32 * ss] * Mk[m * DD + lane + 32 * ss];
        #pragma unroll
        for (int o = 16; o; o >>= 1) s += __shfl_xor_sync(0xFFFFFFFFu, s, o);
        if (lane == 0) logits[m] = s;
    }
    __syncthreads();
    if (tid == 0) {
        float mx = -1e30f;
        for (int m = 0; m < MM; m++) mx = fmaxf(mx, logits[m]);
        red[0] = mx;
    }
    __syncthreads();
    if (tid < MM) logits[tid] = expf(logits[tid] - red[0]);
    __syncthreads();
    if (tid == 0) {
        float s = 0.f;
        for (int m = 0; m < MM; m++) s += logits[m];
        red[1] = 1.f / s;
    }
    __syncthreads();
    if (tid < MM) g_w[bl * MM + tid] = logits[tid] * red[1];

    // e[d] and a[d]: per-thread GEMV rows, float4 vectorized, L1-resident weights
    const float4* v4  = (const float4*)v_s;
    const float4* ew4 = (const float4*)e_W + tid * (DD / 4);
    const float4* aw4 = (const float4*)a_W + tid * (DD / 4);
    float se = e_b[tid], sa = a_b[tid];
    #pragma unroll 8
    for (int j = 0; j < DD / 4; j++) {
        float4 vv = v4[j];
        float4 ee = ew4[j];
        float4 aa = aw4[j];
        se += vv.x * ee.x + vv.y * ee.y + vv.z * ee.z + vv.w * ee.w;
        sa += vv.x * aa.x + vv.y * aa.y + vv.z * aa.z + vv.w * aa.w;
    }
    g_e[bl * DD + tid] = 1.f / (1.f + expf(-se));
    g_a[bl * DD + tid] = tanhf(sa);
}

// ============================================================================
// Kernel B: sequential scan over L. Grid = B*2 (d-halves), 128 threads =
// (m-half 2) x (64 d). Each thread carries Mv[m0..m0+24][d] in registers.
// Writes Mv states (incl. t=0 init) to out, partial reads to g_rp.
// ============================================================================
__global__ void scan_kernel(const float* __restrict__ Mv0,
                            float* __restrict__ mv_out, int write_mv)
{
    int b    = blockIdx.x >> 1;
    int half = blockIdx.x & 1;
    int tid  = threadIdx.x;
    int mh   = tid >> 6;          // 0 or 1 (m half)
    int dl   = tid & 63;
    int d    = half * 64 + dl;
    int m0   = mh * 25;

    float Mv[25];
    #pragma unroll
    for (int i = 0; i < 25; i++) Mv[i] = Mv0[(m0 + i) * DD + d];

    long mv_b = (long)b * 201 * (MM * DD);
    if (write_mv) {
        // t = 0 slice: broadcast of Mv0
        #pragma unroll
        for (int i = 0; i < 25; i++)
            mv_out[mv_b + (m0 + i) * DD + d] = Mv[i];
    }
    long out_base = mv_b + (MM * DD) + (long)m0 * DD + d;   // t=1 element base
    int w_base  = (b * LL) * MM + m0;
    int ea_base = (b * LL) * DD + d;

    for (int t = 0; t < LL; t++) {
        float wt[25];
        #pragma unroll
        for (int i = 0; i < 25; i++) wt[i] = __ldg(&g_w[w_base + t * MM + i]);
        float el = g_e[ea_base + t * DD];
        float al = g_a[ea_base + t * DD];

        // partial read on PRE-update state
        float rp = 0.f;
        #pragma unroll
        for (int i = 0; i < 25; i++) rp += wt[i] * Mv[i];
        g_rp[mh][ea_base + t * DD] = rp;

        // update: Mv = Mv + w*(a - e*Mv)
        #pragma unroll
        for (int i = 0; i < 25; i++)
            Mv[i] = fmaf(wt[i], fmaf(-el, Mv[i], al), Mv[i]);

        if (write_mv) {
            #pragma unroll
            for (int i = 0; i < 25; i++)
                mv_out[out_base + (long)t * (MM * DD) + i * DD] = Mv[i];
        }
    }
}

// ============================================================================
// Kernel C: f = tanh([read, k] f_W^T + f_b); p = sigma(f . p_W + p_b).
// One block per token, 128 threads.
// ============================================================================
__global__ void final_kernel(
    const int* __restrict__ q, const float* __restrict__ k_emb,
    const float* __restrict__ f_W, const float* __restrict__ f_b,
    const float* __restrict__ p_W, const float* __restrict__ p_b,
    float* __restrict__ p_out)
{
    int bl = blockIdx.x;
    int tid = threadIdx.x;
    __shared__ alignas(16) float cat[2 * DD];
    __shared__ float wsum[4];

    cat[tid]      = g_rp[0][bl * DD + tid] + g_rp[1][bl * DD + tid];
    cat[DD + tid] = k_emb[q[bl] * DD + tid];
    __syncthreads();

    const float4* c4  = (const float4*)cat;
    const float4* fw4 = (const float4*)f_W + tid * (2 * DD / 4);
    float s = f_b[tid];
    #pragma unroll 8
    for (int j = 0; j < 2 * DD / 4; j++) {
        float4 c = c4[j];
        float4 w = fw4[j];
        s += c.x * w.x + c.y * w.y + c.z * w.z + c.w * w.w;
    }
    float fd = tanhf(s);
    float val = fd * p_W[tid];
    #pragma unroll
    for (int o = 16; o; o >>= 1) val += __shfl_xor_sync(0xFFFFFFFFu, val, o);
    if ((tid & 31) == 0) wsum[tid >> 5] = val;
    __syncthreads();
    if (tid == 0) {
        float z = wsum[0] + wsum[1] + wsum[2] + wsum[3] + p_b[0];
        p_out[bl] = 1.f / (1.f + expf(-z));
    }
}

// ============================================================================
extern "C" void kernel_launch(void* const* d_in, const int* in_sizes, int n_in,
                              void* d_out, int out_size)
{
    const int*   q     = (const int*)  d_in[0];
    const int*   r     = (const int*)  d_in[1];
    const float* k_emb = (const float*)d_in[2];
    const float* v_emb = (const float*)d_in[3];
    const float* Mk    = (const float*)d_in[4];
    const float* Mv0   = (const float*)d_in[5];
    const float* f_W   = (const float*)d_in[6];
    const float* f_b   = (const float*)d_in[7];
    const float* p_W   = (const float*)d_in[8];
    const float* p_b   = (const float*)d_in[9];
    const float* e_W   = (const float*)d_in[10];
    const float* e_b   = (const float*)d_in[11];
    const float* a_W   = (const float*)d_in[12];
    const float* a_b   = (const float*)d_in[13];

    float* out = (float*)d_out;
    const int  P_CNT  = BB * LL;                       // 12800
    const long MV_CNT = (long)BB * 201 * MM * DD;      // 82,329,600

    float* p_out  = out;
    float* mv_out = out;
    int write_mv  = 0;
    if ((long)out_size >= (long)P_CNT + MV_CNT) {
        mv_out = out + P_CNT;                          // tuple order: (p, Mv)
        write_mv = 1;
    }

    precompute_kernel<<<BB * LL, DD>>>(q, r, k_emb, v_emb, Mk, e_W, e_b, a_W, a_b);
    scan_kernel<<<BB * 2, 128>>>(Mv0, mv_out, write_mv);
    final_kernel<<<BB * LL, DD>>>(q, k_emb, f_W, f_b, p_W, p_b, p_out);
}

// round 3
// speedup vs baseline: 3.3204x; 3.3204x over previous
#include <cuda_runtime.h>
#include <cuda_bf16.h>

#define BB 64
#define LL 200
#define DD 128
#define MM 50
#define NQ 10000
#define TOK 32

// ---- device scratch ----
__device__ float  g_w[BB * LL * MM];          // softmax weights  [B,L,50]
__device__ float  g_e[BB * LL * DD];          // sigmoid gate     [B,L,128]
__device__ float  g_a[BB * LL * DD];          // tanh add         [B,L,128]
__device__ float  g_rp[10][BB * LL * DD];     // partial reads (10 m-groups)
__device__ float2 g_Wea[DD * DD];             // transposed (eW,aW): [j][d]
__device__ float  g_Mkt[DD * 64];             // transposed Mk: [j][m-padded-64]
__device__ float  g_Wtf[2 * DD * DD];         // transposed fW: [j 0..255][d]

// ============================================================================
// Kernel T: one-shot weight transposes (tiny)
// ============================================================================
__global__ void transpose_kernel(const float* __restrict__ eW, const float* __restrict__ aW,
                                 const float* __restrict__ Mk, const float* __restrict__ fW)
{
    int i = blockIdx.x * 256 + threadIdx.x;
    if (i < 16384) {                          // e_W / a_W : [128][128]
        int d = i >> 7, j = i & 127;
        g_Wea[j * 128 + d] = make_float2(eW[i], aW[i]);
    } else if (i < 24576) {                   // Mk : [50][128] -> [128][64]
        int t = i - 16384;
        int j = t >> 6, m = t & 63;
        g_Mkt[t] = (m < MM) ? Mk[m * 128 + j] : 0.f;
    } else if (i < 57344) {                   // f_W : [128][256] -> [256][128]
        int t = i - 24576;
        int d = t >> 8, j = t & 255;
        g_Wtf[j * 128 + d] = fW[t];
    }
}

// ============================================================================
// Kernel A: 32 tokens/block. w = softmax(k Mk^T), e = sigma(v eW^T), a = tanh(v aW^T)
// ============================================================================
__global__ __launch_bounds__(512) void precompute_kernel(
    const int* __restrict__ q, const int* __restrict__ r,
    const float* __restrict__ k_emb, const float* __restrict__ v_emb,
    const float* __restrict__ e_b, const float* __restrict__ a_b)
{
    __shared__ float k_s[TOK * DD];
    __shared__ float v_s[TOK * DD];
    __shared__ float lg_s[TOK * 52];
    __shared__ int qs[TOK], xs[TOK];

    int tid = threadIdx.x;
    int bl0 = blockIdx.x * TOK;

    if (tid < TOK) {
        int qi = q[bl0 + tid];
        qs[tid] = qi;
        xs[tid] = qi + NQ * r[bl0 + tid];
    }
    __syncthreads();

    float4* k4 = (float4*)k_s;
    float4* v4 = (float4*)v_s;
    const float4* ke4 = (const float4*)k_emb;
    const float4* ve4 = (const float4*)v_emb;
    for (int i = tid; i < TOK * 32; i += 512) {
        int tok = i >> 5, j = i & 31;
        k4[i] = ke4[qs[tok] * 32 + j];
        v4[i] = ve4[xs[tok] * 32 + j];
    }
    __syncthreads();

    // ---- logits[tok][m] : threads = (m 0..63) x (8 token-groups of 4) ----
    {
        int m = tid & 63, tg = tid >> 6;
        float a0 = 0.f, a1 = 0.f, a2 = 0.f, a3 = 0.f;
        for (int j4 = 0; j4 < 32; j4++) {
            float mk0 = g_Mkt[(j4 * 4 + 0) * 64 + m];
            float mk1 = g_Mkt[(j4 * 4 + 1) * 64 + m];
            float mk2 = g_Mkt[(j4 * 4 + 2) * 64 + m];
            float mk3 = g_Mkt[(j4 * 4 + 3) * 64 + m];
            float4 c0 = k4[(tg * 4 + 0) * 32 + j4];
            float4 c1 = k4[(tg * 4 + 1) * 32 + j4];
            float4 c2 = k4[(tg * 4 + 2) * 32 + j4];
            float4 c3 = k4[(tg * 4 + 3) * 32 + j4];
            a0 += mk0 * c0.x + mk1 * c0.y + mk2 * c0.z + mk3 * c0.w;
            a1 += mk0 * c1.x + mk1 * c1.y + mk2 * c1.z + mk3 * c1.w;
            a2 += mk0 * c2.x + mk1 * c2.y + mk2 * c2.z + mk3 * c2.w;
            a3 += mk0 * c3.x + mk1 * c3.y + mk2 * c3.z + mk3 * c3.w;
        }
        if (m < MM) {
            lg_s[(tg * 4 + 0) * 52 + m] = a0;
            lg_s[(tg * 4 + 1) * 52 + m] = a1;
            lg_s[(tg * 4 + 2) * 52 + m] = a2;
            lg_s[(tg * 4 + 3) * 52 + m] = a3;
        }
    }
    __syncthreads();

    // ---- softmax: 16 warps x 2 tokens ----
    {
        int wid = tid >> 5, lane = tid & 31;
        for (int tok = wid * 2; tok < wid * 2 + 2; tok++) {
            float v0 = lg_s[tok * 52 + lane];
            float v1 = (lane < MM - 32) ? lg_s[tok * 52 + 32 + lane] : -1e30f;
            float mx = fmaxf(v0, v1);
            #pragma unroll
            for (int o = 16; o; o >>= 1) mx = fmaxf(mx, __shfl_xor_sync(0xFFFFFFFFu, mx, o));
            float e0 = expf(v0 - mx);
            float e1 = (lane < MM - 32) ? expf(v1 - mx) : 0.f;
            float s = e0 + e1;
            #pragma unroll
            for (int o = 16; o; o >>= 1) s += __shfl_xor_sync(0xFFFFFFFFu, s, o);
            float inv = 1.f / s;
            int g = bl0 + tok;
            g_w[g * MM + lane] = e0 * inv;
            if (lane < MM - 32) g_w[g * MM + 32 + lane] = e1 * inv;
        }
    }

    // ---- e/a GEMV: threads = (d 0..127) x (4 token-groups of 8) ----
    {
        int d = tid & 127, tg = tid >> 7;
        float ae[8], aa[8];
        #pragma unroll
        for (int t = 0; t < 8; t++) { ae[t] = 0.f; aa[t] = 0.f; }
        for (int j4 = 0; j4 < 32; j4++) {
            float2 w0 = g_Wea[(j4 * 4 + 0) * 128 + d];
            float2 w1 = g_Wea[(j4 * 4 + 1) * 128 + d];
            float2 w2 = g_Wea[(j4 * 4 + 2) * 128 + d];
            float2 w3 = g_Wea[(j4 * 4 + 3) * 128 + d];
            #pragma unroll
            for (int t = 0; t < 8; t++) {
                float4 v = v4[(tg * 8 + t) * 32 + j4];
                ae[t] += w0.x * v.x + w1.x * v.y + w2.x * v.z + w3.x * v.w;
                aa[t] += w0.y * v.x + w1.y * v.y + w2.y * v.z + w3.y * v.w;
            }
        }
        float eb = e_b[d], ab = a_b[d];
        #pragma unroll
        for (int t = 0; t < 8; t++) {
            int g = bl0 + tg * 8 + t;
            g_e[g * DD + d] = 1.f / (1.f + expf(-(ae[t] + eb)));
            g_a[g * DD + d] = tanhf(aa[t] + ab);
        }
    }
}

// ============================================================================
// Kernel B: sequential scan. grid = 64 b x 2 d-halves; 160 threads =
// (10 m-groups of 5) x (16 float4-d lanes). State in float4 regs, float4 I/O.
// ============================================================================
__global__ void scan_kernel(const float* __restrict__ Mv0,
                            float* __restrict__ mv_out, int write_mv)
{
    int b   = blockIdx.x >> 1;
    int dh  = blockIdx.x & 1;
    int tid = threadIdx.x;
    int l16 = tid & 15;
    int mg  = tid >> 4;          // 0..9
    int m0  = mg * 5;
    int d   = dh * 64 + l16 * 4;

    const float4* Mv04 = (const float4*)Mv0;
    float4 S[5];
    #pragma unroll
    for (int i = 0; i < 5; i++) S[i] = Mv04[((m0 + i) * DD + d) >> 2];

    float4* out4 = (float4*)mv_out;
    long base201 = (long)b * 201 * (MM * DD);
    if (write_mv) {
        #pragma unroll
        for (int i = 0; i < 5; i++)
            out4[(base201 + (m0 + i) * DD + d) >> 2] = S[i];
    }

    const float4* e4p = (const float4*)g_e;
    const float4* a4p = (const float4*)g_a;
    float4* rp4 = (float4*)g_rp[mg];
    int  wbase  = (b * LL) * MM + m0;
    int  eabase = ((b * LL) * DD + d) >> 2;
    long obase  = base201 + MM * DD;

    for (int t = 0; t < LL; t++) {
        float wv[5];
        #pragma unroll
        for (int i = 0; i < 5; i++) wv[i] = g_w[wbase + t * MM + i];
        float4 e = e4p[eabase + t * 32];
        float4 a = a4p[eabase + t * 32];

        float4 rp = make_float4(0.f, 0.f, 0.f, 0.f);
        #pragma unroll
        for (int i = 0; i < 5; i++) {
            rp.x += wv[i] * S[i].x;
            rp.y += wv[i] * S[i].y;
            rp.z += wv[i] * S[i].z;
            rp.w += wv[i] * S[i].w;
        }
        rp4[eabase + t * 32] = rp;

        #pragma unroll
        for (int i = 0; i < 5; i++) {
            S[i].x = fmaf(wv[i], fmaf(-e.x, S[i].x, a.x), S[i].x);
            S[i].y = fmaf(wv[i], fmaf(-e.y, S[i].y, a.y), S[i].y);
            S[i].z = fmaf(wv[i], fmaf(-e.z, S[i].z, a.z), S[i].z);
            S[i].w = fmaf(wv[i], fmaf(-e.w, S[i].w, a.w), S[i].w);
        }
        if (write_mv) {
            long ob = obase + (long)t * (MM * DD);
            #pragma unroll
            for (int i = 0; i < 5; i++)
                out4[(ob + (m0 + i) * DD + d) >> 2] = S[i];
        }
    }
}

// ============================================================================
// Kernel C: 32 tokens/block. f = tanh([read,k] fW^T + fb); p = sigma(f . pW + pb)
// Reuses cat_s for the f-value reduction (stays under 48KB static smem).
// ============================================================================
__global__ __launch_bounds__(512) void final_kernel(
    const int* __restrict__ q, const float* __restrict__ k_emb,
    const float* __restrict__ f_b, const float* __restrict__ p_W,
    const float* __restrict__ p_b, float* __restrict__ p_out)
{
    __shared__ float cat_s[TOK * 256];
    __shared__ int qs[TOK];

    int tid = threadIdx.x;
    int bl0 = blockIdx.x * TOK;

    if (tid < TOK) qs[tid] = q[bl0 + tid];
    __syncthreads();

    float4* cat4 = (float4*)cat_s;
    const float4* ke4 = (const float4*)k_emb;
    for (int i = tid; i < TOK * 32; i += 512) {
        int tok = i >> 5, j4 = i & 31;
        int gi = ((bl0 + tok) * DD >> 2) + j4;
        float4 s = make_float4(0.f, 0.f, 0.f, 0.f);
        #pragma unroll
        for (int mg = 0; mg < 10; mg++) {
            float4 v = ((const float4*)g_rp[mg])[gi];
            s.x += v.x; s.y += v.y; s.z += v.z; s.w += v.w;
        }
        cat4[tok * 64 + j4] = s;                            // read part
        cat4[tok * 64 + 32 + j4] = ke4[qs[tok] * 32 + j4];  // k part
    }
    __syncthreads();

    // GEMV over 256 inputs: threads = (d 0..127) x (4 token-groups of 8)
    int d = tid & 127, tg = tid >> 7;
    float acc[8];
    #pragma unroll
    for (int t = 0; t < 8; t++) acc[t] = 0.f;
    for (int j4 = 0; j4 < 64; j4++) {
        float w0 = g_Wtf[(j4 * 4 + 0) * 128 + d];
        float w1 = g_Wtf[(j4 * 4 + 1) * 128 + d];
        float w2 = g_Wtf[(j4 * 4 + 2) * 128 + d];
        float w3 = g_Wtf[(j4 * 4 + 3) * 128 + d];
        #pragma unroll
        for (int t = 0; t < 8; t++) {
            float4 c = cat4[(tg * 8 + t) * 64 + j4];
            acc[t] += w0 * c.x + w1 * c.y + w2 * c.z + w3 * c.w;
        }
    }
    float fb = f_b[d], pw = p_W[d];
    __syncthreads();   // all GEMV reads of cat_s done; now reuse it for f values
    #pragma unroll
    for (int t = 0; t < 8; t++)
        cat_s[(tg * 8 + t) * 128 + d] = tanhf(acc[t] + fb) * pw;
    __syncthreads();

    // reduce over d: 16 warps x 2 tokens
    {
        int wid = tid >> 5, lane = tid & 31;
        float pb = p_b[0];
        for (int tok = wid * 2; tok < wid * 2 + 2; tok++) {
            float s = cat_s[tok * 128 + lane] + cat_s[tok * 128 + lane + 32]
                    + cat_s[tok * 128 + lane + 64] + cat_s[tok * 128 + lane + 96];
            #pragma unroll
            for (int o = 16; o; o >>= 1) s += __shfl_xor_sync(0xFFFFFFFFu, s, o);
            if (lane == 0) p_out[bl0 + tok] = 1.f / (1.f + expf(-(s + pb)));
        }
    }
}

// ============================================================================
extern "C" void kernel_launch(void* const* d_in, const int* in_sizes, int n_in,
                              void* d_out, int out_size)
{
    const int*   q     = (const int*)  d_in[0];
    const int*   r     = (const int*)  d_in[1];
    const float* k_emb = (const float*)d_in[2];
    const float* v_emb = (const float*)d_in[3];
    const float* Mk    = (const float*)d_in[4];
    const float* Mv0   = (const float*)d_in[5];
    const float* f_W   = (const float*)d_in[6];
    const float* f_b   = (const float*)d_in[7];
    const float* p_W   = (const float*)d_in[8];
    const float* p_b   = (const float*)d_in[9];
    const float* e_W   = (const float*)d_in[10];
    const float* e_b   = (const float*)d_in[11];
    const float* a_W   = (const float*)d_in[12];
    const float* a_b   = (const float*)d_in[13];

    float* out = (float*)d_out;
    const int  P_CNT  = BB * LL;                     // 12800
    const long MV_CNT = (long)BB * 201 * MM * DD;    // 82,329,600

    float* p_out  = out;
    float* mv_out = out;
    int write_mv  = 0;
    if ((long)out_size >= (long)P_CNT + MV_CNT) {
        mv_out = out + P_CNT;
        write_mv = 1;
    }

    transpose_kernel<<<224, 256>>>(e_W, a_W, Mk, f_W);
    precompute_kernel<<<BB * LL / TOK, 512>>>(q, r, k_emb, v_emb, e_b, a_b);
    scan_kernel<<<BB * 2, 160>>>(Mv0, mv_out, write_mv);
    final_kernel<<<BB * LL / TOK, 512>>>(q, k_emb, f_b, p_W, p_b, p_out);
}

// round 5
// speedup vs baseline: 3.8770x; 1.1676x over previous
#include <cuda_runtime.h>
#include <cuda_bf16.h>

#define BB 64
#define LL 200
#define DD 128
#define MM 50
#define NQ 10000
#define TOK 32

// ---- device scratch ----
__device__ float  g_w[BB * LL * MM];       // softmax weights  [B,L,50]
__device__ float  g_e[BB * LL * DD];       // sigmoid gate     [B,L,128]
__device__ float  g_a[BB * LL * DD];       // tanh add         [B,L,128]
__device__ float  g_rp[BB * LL * DD];      // fully-reduced read [B,L,128]
__device__ float4 g_We4[32 * DD];          // eW packed: [j4][d] = eW[d][4j4..4j4+3]
__device__ float4 g_Wa4[32 * DD];          // aW packed
__device__ float4 g_Mk4[32 * 64];          // Mk packed: [j4][m(pad64)]
__device__ float4 g_Wf4[64 * DD];          // fW packed: [j4 0..63][d]

// ---- packed f32x2 FMA (Blackwell) ----
__device__ __forceinline__ float2 ffma2(float2 a, float2 b, float2 c) {
    float2 d;
    asm("fma.rn.f32x2 %0, %1, %2, %3;"
        : "=l"(*reinterpret_cast<unsigned long long*>(&d))
        : "l"(*reinterpret_cast<unsigned long long*>(&a)),
          "l"(*reinterpret_cast<unsigned long long*>(&b)),
          "l"(*reinterpret_cast<unsigned long long*>(&c)));
    return d;
}
__device__ __forceinline__ float2 f2(float x, float y) { return make_float2(x, y); }

// ============================================================================
// Kernel T: weight transposes into packed-j4 layouts (coalesced float4 reads)
// ============================================================================
__global__ void transpose_kernel(const float* __restrict__ eW, const float* __restrict__ aW,
                                 const float* __restrict__ Mk, const float* __restrict__ fW)
{
    int i = blockIdx.x * 256 + threadIdx.x;
    if (i < 4096) {                       // e_W,a_W: [128 d][32 j4]
        int d = i >> 5, j4 = i & 31;
        g_We4[j4 * 128 + d] = ((const float4*)eW)[d * 32 + j4];
        g_Wa4[j4 * 128 + d] = ((const float4*)aW)[d * 32 + j4];
    } else if (i < 6144) {                // Mk: [50 m][32 j4] -> [32 j4][64 m]
        int t = i - 4096;
        int m = t >> 5, j4 = t & 31;
        g_Mk4[j4 * 64 + m] = (m < MM) ? ((const float4*)Mk)[m * 32 + j4]
                                      : make_float4(0.f, 0.f, 0.f, 0.f);
    } else if (i < 14336) {               // f_W: [128 d][64 j4] -> [64 j4][128 d]
        int t = i - 6144;
        int d = t >> 6, j4 = t & 63;
        g_Wf4[j4 * 128 + d] = ((const float4*)fW)[d * 64 + j4];
    }
}

// ============================================================================
// Kernel A: 32 tokens/block. w = softmax(k Mk^T), e = sigma(v eW^T), a = tanh(v aW^T)
// ============================================================================
__global__ __launch_bounds__(512) void precompute_kernel(
    const int* __restrict__ q, const int* __restrict__ r,
    const float* __restrict__ k_emb, const float* __restrict__ v_emb,
    const float* __restrict__ e_b, const float* __restrict__ a_b)
{
    __shared__ float k_s[TOK * DD];
    __shared__ float v_s[TOK * DD];
    __shared__ float lg_s[TOK * 52];
    __shared__ int qs[TOK], xs[TOK];

    int tid = threadIdx.x;
    int bl0 = blockIdx.x * TOK;

    if (tid < TOK) {
        int qi = q[bl0 + tid];
        qs[tid] = qi;
        xs[tid] = qi + NQ * r[bl0 + tid];
    }
    __syncthreads();

    float4* k4 = (float4*)k_s;
    float4* v4 = (float4*)v_s;
    const float4* ke4 = (const float4*)k_emb;
    const float4* ve4 = (const float4*)v_emb;
    for (int i = tid; i < TOK * 32; i += 512) {
        int tok = i >> 5, j = i & 31;
        k4[i] = ke4[qs[tok] * 32 + j];
        v4[i] = ve4[xs[tok] * 32 + j];
    }
    __syncthreads();

    // ---- logits: threads = (m 0..63) x (8 token-groups of 4), f32x2 FMA ----
    {
        int m = tid & 63, tg = tid >> 6;
        float2 a0 = f2(0, 0), a1 = f2(0, 0), a2 = f2(0, 0), a3 = f2(0, 0);
        for (int j4 = 0; j4 < 32; j4++) {
            float4 mk = g_Mk4[j4 * 64 + m];
            float2 mlo = f2(mk.x, mk.y), mhi = f2(mk.z, mk.w);
            float4 c0 = k4[(tg * 4 + 0) * 32 + j4];
            float4 c1 = k4[(tg * 4 + 1) * 32 + j4];
            float4 c2 = k4[(tg * 4 + 2) * 32 + j4];
            float4 c3 = k4[(tg * 4 + 3) * 32 + j4];
            a0 = ffma2(mlo, f2(c0.x, c0.y), a0); a0 = ffma2(mhi, f2(c0.z, c0.w), a0);
            a1 = ffma2(mlo, f2(c1.x, c1.y), a1); a1 = ffma2(mhi, f2(c1.z, c1.w), a1);
            a2 = ffma2(mlo, f2(c2.x, c2.y), a2); a2 = ffma2(mhi, f2(c2.z, c2.w), a2);
            a3 = ffma2(mlo, f2(c3.x, c3.y), a3); a3 = ffma2(mhi, f2(c3.z, c3.w), a3);
        }
        if (m < MM) {
            lg_s[(tg * 4 + 0) * 52 + m] = a0.x + a0.y;
            lg_s[(tg * 4 + 1) * 52 + m] = a1.x + a1.y;
            lg_s[(tg * 4 + 2) * 52 + m] = a2.x + a2.y;
            lg_s[(tg * 4 + 3) * 52 + m] = a3.x + a3.y;
        }
    }
    __syncthreads();

    // ---- softmax: 16 warps x 2 tokens ----
    {
        int wid = tid >> 5, lane = tid & 31;
        for (int tok = wid * 2; tok < wid * 2 + 2; tok++) {
            float v0 = lg_s[tok * 52 + lane];
            float v1 = (lane < MM - 32) ? lg_s[tok * 52 + 32 + lane] : -1e30f;
            float mx = fmaxf(v0, v1);
            #pragma unroll
            for (int o = 16; o; o >>= 1) mx = fmaxf(mx, __shfl_xor_sync(0xFFFFFFFFu, mx, o));
            float e0 = expf(v0 - mx);
            float e1 = (lane < MM - 32) ? expf(v1 - mx) : 0.f;
            float s = e0 + e1;
            #pragma unroll
            for (int o = 16; o; o >>= 1) s += __shfl_xor_sync(0xFFFFFFFFu, s, o);
            float inv = 1.f / s;
            int g = bl0 + tok;
            g_w[g * MM + lane] = e0 * inv;
            if (lane < MM - 32) g_w[g * MM + 32 + lane] = e1 * inv;
        }
    }

    // ---- e/a GEMV: threads = (d 0..127) x (4 token-groups of 8), f32x2 ----
    {
        int d = tid & 127, tg = tid >> 7;
        float2 ae[8], aa[8];
        #pragma unroll
        for (int t = 0; t < 8; t++) { ae[t] = f2(0, 0); aa[t] = f2(0, 0); }
        for (int j4 = 0; j4 < 32; j4++) {
            float4 we = g_We4[j4 * 128 + d];
            float4 wa = g_Wa4[j4 * 128 + d];
            float2 welo = f2(we.x, we.y), wehi = f2(we.z, we.w);
            float2 walo = f2(wa.x, wa.y), wahi = f2(wa.z, wa.w);
            #pragma unroll
            for (int t = 0; t < 8; t++) {
                float4 v = v4[(tg * 8 + t) * 32 + j4];
                float2 vlo = f2(v.x, v.y), vhi = f2(v.z, v.w);
                ae[t] = ffma2(welo, vlo, ae[t]); ae[t] = ffma2(wehi, vhi, ae[t]);
                aa[t] = ffma2(walo, vlo, aa[t]); aa[t] = ffma2(wahi, vhi, aa[t]);
            }
        }
        float eb = e_b[d], ab = a_b[d];
        #pragma unroll
        for (int t = 0; t < 8; t++) {
            int g = bl0 + tg * 8 + t;
            g_e[g * DD + d] = 1.f / (1.f + expf(-(ae[t].x + ae[t].y + eb)));
            g_a[g * DD + d] = tanhf(aa[t].x + aa[t].y + ab);
        }
    }
}

// ============================================================================
// Kernel B: sequential scan. grid = 64 b x 2 d-halves; 160 threads =
// (10 m-groups of 5) x (16 float4-d lanes). Prefetched loads, f32x2 math,
// in-block rp reduction (double-buffered smem, 1 sync/step).
// ============================================================================
__global__ void scan_kernel(const float* __restrict__ Mv0,
                            float* __restrict__ mv_out, int write_mv)
{
    __shared__ float4 sm_rp[2][10][16];

    int b   = blockIdx.x >> 1;
    int dh  = blockIdx.x & 1;
    int tid = threadIdx.x;
    int l16 = tid & 15;
    int mg  = tid >> 4;          // 0..9
    int m0  = mg * 5;
    int d   = dh * 64 + l16 * 4;

    const float4* Mv04 = (const float4*)Mv0;
    float2 Slo[5], Shi[5];
    #pragma unroll
    for (int i = 0; i < 5; i++) {
        float4 s = Mv04[((m0 + i) * DD + d) >> 2];
        Slo[i] = f2(s.x, s.y);
        Shi[i] = f2(s.z, s.w);
    }

    float4* out4 = (float4*)mv_out;
    long base201 = (long)b * 201 * (MM * DD);
    if (write_mv) {
        #pragma unroll
        for (int i = 0; i < 5; i++)
            out4[(base201 + (m0 + i) * DD + d) >> 2] =
                make_float4(Slo[i].x, Slo[i].y, Shi[i].x, Shi[i].y);
    }

    const float4* e4p = (const float4*)g_e;
    const float4* a4p = (const float4*)g_a;
    int  wbase  = (b * LL) * MM + m0;
    int  eabase = ((b * LL) * DD + d) >> 2;
    long obase  = base201 + MM * DD;
    int  rpbase = (b * LL) * DD + dh * 64;

    // prefetch t = 0
    float wv[5];
    #pragma unroll
    for (int i = 0; i < 5; i++) wv[i] = g_w[wbase + i];
    float4 ecur = e4p[eabase];
    float4 acur = a4p[eabase];

    for (int t = 0; t < LL; t++) {
        // prefetch t+1
        int tn = (t + 1 < LL) ? t + 1 : t;
        float wn[5];
        #pragma unroll
        for (int i = 0; i < 5; i++) wn[i] = g_w[wbase + tn * MM + i];
        float4 en = e4p[eabase + tn * 32];
        float4 an = a4p[eabase + tn * 32];

        float2 nelo = f2(-ecur.x, -ecur.y), nehi = f2(-ecur.z, -ecur.w);
        float2 alo  = f2(acur.x, acur.y),   ahi  = f2(acur.z, acur.w);
        float2 rlo  = f2(0.f, 0.f),         rhi  = f2(0.f, 0.f);

        long ob = obase + (long)t * (MM * DD);
        #pragma unroll
        for (int i = 0; i < 5; i++) {
            float2 w2 = f2(wv[i], wv[i]);
            rlo = ffma2(w2, Slo[i], rlo);
            rhi = ffma2(w2, Shi[i], rhi);
            float2 tlo = ffma2(nelo, Slo[i], alo);
            float2 thi = ffma2(nehi, Shi[i], ahi);
            Slo[i] = ffma2(w2, tlo, Slo[i]);
            Shi[i] = ffma2(w2, thi, Shi[i]);
            if (write_mv)
                out4[(ob + (m0 + i) * DD + d) >> 2] =
                    make_float4(Slo[i].x, Slo[i].y, Shi[i].x, Shi[i].y);
        }

        sm_rp[t & 1][mg][l16] = make_float4(rlo.x, rlo.y, rhi.x, rhi.y);
        __syncthreads();
        if (tid < 64) {
            const float* sp = (const float*)sm_rp[t & 1];
            float s = 0.f;
            #pragma unroll
            for (int g = 0; g < 10; g++) s += sp[g * 64 + tid];
            g_rp[rpbase + t * DD + tid] = s;
        }
        // Single barrier per step is safe: buffer t&1 is read between the
        // barriers at t and t+1, and next rewritten only at t+2, which is
        // after the t+1 barrier that the reducer threads also join.

        #pragma unroll
        for (int i = 0; i < 5; i++) wv[i] = wn[i];
        ecur = en;
        acur = an;
    }
}

// ============================================================================
// Kernel C: 32 tokens/block. f = tanh([read,k] fW^T + fb); p = sigma(f . pW + pb)
// ============================================================================
__global__ __launch_bounds__(512) void final_kernel(
    const int* __restrict__ q, const float* __restrict__ k_emb,
    const float* __restrict__ f_b, const float* __restrict__ p_W,
    const float* __restrict__ p_b, float* __restrict__ p_out)
{
    __shared__ float cat_s[TOK * 256];
    __shared__ int qs[TOK];

    int tid = threadIdx.x;
    int bl0 = blockIdx.x * TOK;

    if (tid < TOK) qs[tid] = q[bl0 + tid];
    __syncthreads();

    float4* cat4 = (float4*)cat_s;
    const float4* ke4 = (const float4*)k_emb;
    const float4* rp4 = (const float4*)g_rp;
    for (int i = tid; i < TOK * 32; i += 512) {
        int tok = i >> 5, j4 = i & 31;
        cat4[tok * 64 + j4]      = rp4[(bl0 + tok) * 32 + j4];   // read part
        cat4[tok * 64 + 32 + j4] = ke4[qs[tok] * 32 + j4];       // k part
    }
    __syncthreads();

    // GEMV over 256 inputs: threads = (d 0..127) x (4 token-groups of 8), f32x2
    int d = tid & 127, tg = tid >> 7;
    float2 acc[8];
    #pragma unroll
    for (int t = 0; t < 8; t++) acc[t] = f2(0, 0);
    for (int j4 = 0; j4 < 64; j4++) {
        float4 w = g_Wf4[j4 * 128 + d];
        float2 wlo = f2(w.x, w.y), whi = f2(w.z, w.w);
        #pragma unroll
        for (int t = 0; t < 8; t++) {
            float4 c = cat4[(tg * 8 + t) * 64 + j4];
            acc[t] = ffma2(wlo, f2(c.x, c.y), acc[t]);
            acc[t] = ffma2(whi, f2(c.z, c.w), acc[t]);
        }
    }
    float fb = f_b[d], pw = p_W[d];
    __syncthreads();   // all reads of cat_s done; reuse for f values
    #pragma unroll
    for (int t = 0; t < 8; t++)
        cat_s[(tg * 8 + t) * 128 + d] = tanhf(acc[t].x + acc[t].y + fb) * pw;
    __syncthreads();

    // reduce over d: 16 warps x 2 tokens
    {
        int wid = tid >> 5, lane = tid & 31;
        float pb = p_b[0];
        for (int tok = wid * 2; tok < wid * 2 + 2; tok++) {
            float s = cat_s[tok * 128 + lane] + cat_s[tok * 128 + lane + 32]
                    + cat_s[tok * 128 + lane + 64] + cat_s[tok * 128 + lane + 96];
            #pragma unroll
            for (int o = 16; o; o >>= 1) s += __shfl_xor_sync(0xFFFFFFFFu, s, o);
            if (lane == 0) p_out[bl0 + tok] = 1.f / (1.f + expf(-(s + pb)));
        }
    }
}

// ============================================================================
extern "C" void kernel_launch(void* const* d_in, const int* in_sizes, int n_in,
                              void* d_out, int out_size)
{
    const int*   q     = (const int*)  d_in[0];
    const int*   r     = (const int*)  d_in[1];
    const float* k_emb = (const float*)d_in[2];
    const float* v_emb = (const float*)d_in[3];
    const float* Mk    = (const float*)d_in[4];
    const float* Mv0   = (const float*)d_in[5];
    const float* f_W   = (const float*)d_in[6];
    const float* f_b   = (const float*)d_in[7];
    const float* p_W   = (const float*)d_in[8];
    const float* p_b   = (const float*)d_in[9];
    const float* e_W   = (const float*)d_in[10];
    const float* e_b   = (const float*)d_in[11];
    const float* a_W   = (const float*)d_in[12];
    const float* a_b   = (const float*)d_in[13];

    float* out = (float*)d_out;
    const int  P_CNT  = BB * LL;                     // 12800
    const long MV_CNT = (long)BB * 201 * MM * DD;    // 82,329,600

    float* p_out  = out;
    float* mv_out = out;
    int write_mv  = 0;
    if ((long)out_size >= (long)P_CNT + MV_CNT) {
        mv_out = out + P_CNT;
        write_mv = 1;
    }

    transpose_kernel<<<56, 256>>>(e_W, a_W, Mk, f_W);
    precompute_kernel<<<BB * LL / TOK, 512>>>(q, r, k_emb, v_emb, e_b, a_b);
    scan_kernel<<<BB * 2, 160>>>(Mv0, mv_out, write_mv);
    final_kernel<<<BB * LL / TOK, 512>>>(q, k_emb, f_b, p_W, p_b, p_out);
}